// round 15
// baseline (speedup 1.0000x reference)
#include <cuda_runtime.h>
#include <math.h>

// ---------------------------------------------------------------------------
// SwitchMoE: B=8,T=2048,D=1024,F=4096,E=16 -> tokens=16384
// capacity=1280, K=13. Only per-expert rank%1280==0 tokens are processed
// (~1/expert). nonzero(size=K, fill_value=0) artifact: token 0's expert
// output is scaled by (K - kept_e0 + 1). Kept tokens are unique -> plain
// stores into zeroed output (zeroing fused into router).
// ---------------------------------------------------------------------------

#define TOKENS 16384
#define DD     1024
#define EE     16
#define FF     4096
#define CAP    1280
#define KK     13
#define NW     (EE * KK)          /* 208 */
#define RBLK   1024               /* router blocks (16 tokens each) */

// ---- device scratch (no allocations allowed) ------------------------------
__device__ int   g_top1[TOKENS];
__device__ float g_top1p[TOKENS];
__device__ float g_part[RBLK * EE];      // per-block softmax partial sums
__device__ int   g_wtok[NW];
__device__ float g_wscale[NW];
__device__ float g_h[(size_t)NW * FF];   // ~3.4 MB

// ---------------------------------------------------------------------------
// Router: 16 tokens/block (8 warps x 2 tokens). Wr staged in shared (two
// 8-expert passes, 32KB); x rows in registers so each LDS.128 feeds 8 FMAs.
// No atomics: per-block prob sums reduced through shared -> g_part.
// Also zeroes this block's 16 output rows.
// ---------------------------------------------------------------------------
__global__ void __launch_bounds__(256)
router_kernel(const float* __restrict__ x,
              const float* __restrict__ Wr,
              float* __restrict__ out) {
    __shared__ float sWr[8 * DD];        // 32 KB
    __shared__ float sProbs[16][EE + 1]; // padded vs bank conflicts

    const int tid  = threadIdx.x;
    const int warp = tid >> 5;
    const int lane = tid & 31;
    const int tBase = blockIdx.x * 16;
    const int t0 = tBase + warp * 2;

    // zero the 16 output rows this block owns
    {
        float4* o = (float4*)(out + (size_t)tBase * DD);
        const float4 z = make_float4(0.f, 0.f, 0.f, 0.f);
        #pragma unroll
        for (int j = tid; j < 16 * DD / 4; j += 256) o[j] = z;
    }

    // x rows for the warp's two tokens -> registers
    float4 xa[8], xb[8];
    {
        const float4* X0 = (const float4*)(x + (size_t)t0 * DD);
        const float4* X1 = (const float4*)(x + (size_t)(t0 + 1) * DD);
        #pragma unroll
        for (int i = 0; i < 8; i++) { xa[i] = X0[lane + i * 32]; xb[i] = X1[lane + i * 32]; }
    }

    float acc0[EE], acc1[EE];
    #pragma unroll
    for (int e = 0; e < EE; e++) { acc0[e] = 0.f; acc1[e] = 0.f; }

    #pragma unroll
    for (int pass = 0; pass < 2; pass++) {
        __syncthreads();
        {
            const float4* wsrc = (const float4*)(Wr + (size_t)pass * 8 * DD);
            float4* sdst = (float4*)sWr;
            #pragma unroll
            for (int j = tid; j < 8 * DD / 4; j += 256) sdst[j] = wsrc[j];
        }
        __syncthreads();
        #pragma unroll
        for (int e8 = 0; e8 < 8; e8++) {
            const float4* w = (const float4*)(sWr + e8 * DD);
            float s0 = 0.f, s1 = 0.f;
            #pragma unroll
            for (int i = 0; i < 8; i++) {
                float4 wv = w[lane + i * 32];
                s0 += xa[i].x * wv.x + xa[i].y * wv.y + xa[i].z * wv.z + xa[i].w * wv.w;
                s1 += xb[i].x * wv.x + xb[i].y * wv.y + xb[i].z * wv.z + xb[i].w * wv.w;
            }
            acc0[pass * 8 + e8] += s0;
            acc1[pass * 8 + e8] += s1;
        }
    }

    // reduce partial logits across the warp
    #pragma unroll
    for (int off = 16; off; off >>= 1) {
        #pragma unroll
        for (int e = 0; e < EE; e++) {
            acc0[e] += __shfl_xor_sync(0xffffffffu, acc0[e], off);
            acc1[e] += __shfl_xor_sync(0xffffffffu, acc1[e], off);
        }
    }

    if (lane < 2) {
        const float* a = lane ? acc1 : acc0;
        const int t = t0 + lane;
        float m = a[0]; int am = 0;
        #pragma unroll
        for (int e = 1; e < EE; e++) if (a[e] > m) { m = a[e]; am = e; }
        float p[EE];
        float s = 0.f;
        #pragma unroll
        for (int e = 0; e < EE; e++) { p[e] = expf(a[e] - m); s += p[e]; }
        const float inv = 1.0f / s;
        g_top1[t]  = am;
        g_top1p[t] = p[am] * inv;
        #pragma unroll
        for (int e = 0; e < EE; e++) sProbs[warp * 2 + lane][e] = p[e] * inv;
    }
    __syncthreads();
    if (tid < EE) {
        float s = 0.f;
        #pragma unroll
        for (int j = 0; j < 16; j++) s += sProbs[j][tid];
        g_part[blockIdx.x * EE + tid] = s;
    }
}

// ---------------------------------------------------------------------------
// Scan: 1 block, 16 warps; warp e walks tokens in order via ballot (exact
// in-order ranks), records rank%CAP==0 tokens, applies the token-0 fill
// multiplier, reduces g_part -> lb_loss.
// ---------------------------------------------------------------------------
__global__ void __launch_bounds__(512)
scan_kernel(float* __restrict__ out, int out_size) {
    const int tid  = threadIdx.x;
    const int e    = tid >> 5;
    const int lane = tid & 31;
    __shared__ int   sCnt[EE];
    __shared__ float sPsum[EE];

    if (tid < EE) sPsum[tid] = 0.f;
    if (lane < KK) { g_wtok[e * KK + lane] = -1; g_wscale[e * KK + lane] = 0.f; }

    int cnt = 0;
    #pragma unroll 16
    for (int base = 0; base < TOKENS; base += 32) {
        const int t = base + lane;
        const bool m = (g_top1[t] == e);
        const unsigned msk = __ballot_sync(0xffffffffu, m);
        if (m) {
            const int r = cnt + __popc(msk & ((1u << lane) - 1u));
            if (r % CAP == 0) {
                const int slot = r / CAP;
                g_wtok[e * KK + slot]   = t;
                g_wscale[e * KK + slot] = g_top1p[t];
            }
        }
        cnt += __popc(msk);
    }
    if (lane == 0) sCnt[e] = cnt;

    // reduce g_part[1024][16]: thread tid covers expert tid&15, chunks tid>>4
    __syncthreads();
    {
        const int ee = tid & 15;
        float s = 0.f;
        for (int i = tid >> 4; i < RBLK; i += 32)
            s += g_part[i * EE + ee];
        atomicAdd(&sPsum[ee], s);
    }
    __syncthreads();

    if (tid == 0) {
        const int e0 = g_top1[0];
        const int c0 = sCnt[e0];
        const int kept0 = (c0 - 1) / CAP + 1;
        g_wscale[e0 * KK + 0] *= (float)(KK - kept0 + 1);

        if (out_size > TOKENS * DD) {
            float lb = 0.f;
            for (int j = 0; j < EE; j++)
                lb += ((float)sCnt[j] / (float)TOKENS) * (sPsum[j] / (float)TOKENS);
            out[(size_t)TOKENS * DD] = lb * (float)EE * 0.01f;
        }
    }
}

// ---------------------------------------------------------------------------
// FFN1: h = gelu(W1[e] @ x[t] + b1[e]); warp handles rows f and f+F/2
// (16 outstanding LDG.128 per lane). grid(F/16, E).
// ---------------------------------------------------------------------------
__global__ void __launch_bounds__(256)
ffn1_kernel(const float* __restrict__ x,
            const float* __restrict__ W1,
            const float* __restrict__ b1) {
    __shared__ float sx[DD];   // 4 KB
    const int tid  = threadIdx.x;
    const int warp = tid >> 5;
    const int lane = tid & 31;
    const int e    = blockIdx.y;
    const int f0   = blockIdx.x * 8 + warp;
    const int f1   = f0 + FF / 2;

    for (int k = 0; k < KK; k++) {
        const int t = g_wtok[e * KK + k];
        if (t < 0) break;
        __syncthreads();
        ((float4*)sx)[tid] = ((const float4*)(x + (size_t)t * DD))[tid];
        __syncthreads();

        const float4* w0 = (const float4*)(W1 + ((size_t)e * FF + f0) * DD);
        const float4* w1 = (const float4*)(W1 + ((size_t)e * FF + f1) * DD);
        const float4* xv = (const float4*)sx;
        float s0 = 0.f, s1 = 0.f;
        #pragma unroll
        for (int i = 0; i < 8; i++) {
            const float4 a = w0[lane + i * 32];
            const float4 b = w1[lane + i * 32];
            const float4 xx = xv[lane + i * 32];
            s0 += a.x * xx.x + a.y * xx.y + a.z * xx.z + a.w * xx.w;
            s1 += b.x * xx.x + b.y * xx.y + b.z * xx.z + b.w * xx.w;
        }
        #pragma unroll
        for (int off = 16; off; off >>= 1) {
            s0 += __shfl_xor_sync(0xffffffffu, s0, off);
            s1 += __shfl_xor_sync(0xffffffffu, s1, off);
        }
        if (lane == 0) {
            float* hrow = g_h + ((size_t)(e * KK + k)) * FF;
            const float v0 = s0 + b1[e * FF + f0];
            const float v1 = s1 + b1[e * FF + f1];
            hrow[f0] = 0.5f * v0 * (1.0f + erff(v0 * 0.70710678118654752f));
            hrow[f1] = 0.5f * v1 * (1.0f + erff(v1 * 0.70710678118654752f));
        }
    }
}

// ---------------------------------------------------------------------------
// FFN2: out[t] = (W2[e] @ h + b2[e]) * scale; warp handles rows d and d+D/2.
// Kept tokens unique across experts -> plain store. grid(D/16, E).
// ---------------------------------------------------------------------------
__global__ void __launch_bounds__(256)
ffn2_kernel(const float* __restrict__ W2,
            const float* __restrict__ b2,
            float* __restrict__ out) {
    __shared__ float sh[FF];   // 16 KB
    const int tid  = threadIdx.x;
    const int warp = tid >> 5;
    const int lane = tid & 31;
    const int e    = blockIdx.y;
    const int d0   = blockIdx.x * 8 + warp;
    const int d1   = d0 + DD / 2;

    for (int k = 0; k < KK; k++) {
        const int t = g_wtok[e * KK + k];
        if (t < 0) break;
        const float scale = g_wscale[e * KK + k];
        __syncthreads();
        {
            const float4* hs = (const float4*)(g_h + ((size_t)(e * KK + k)) * FF);
            float4* sd = (float4*)sh;
            #pragma unroll
            for (int j = tid; j < FF / 4; j += 256) sd[j] = hs[j];
        }
        __syncthreads();

        const float4* w0 = (const float4*)(W2 + ((size_t)e * DD + d0) * FF);
        const float4* w1 = (const float4*)(W2 + ((size_t)e * DD + d1) * FF);
        const float4* hv = (const float4*)sh;
        float s0 = 0.f, s1 = 0.f;
        #pragma unroll 8
        for (int i = 0; i < 32; i++) {
            const float4 a = w0[lane + i * 32];
            const float4 b = w1[lane + i * 32];
            const float4 hh = hv[lane + i * 32];
            s0 += a.x * hh.x + a.y * hh.y + a.z * hh.z + a.w * hh.w;
            s1 += b.x * hh.x + b.y * hh.y + b.z * hh.z + b.w * hh.w;
        }
        #pragma unroll
        for (int off = 16; off; off >>= 1) {
            s0 += __shfl_xor_sync(0xffffffffu, s0, off);
            s1 += __shfl_xor_sync(0xffffffffu, s1, off);
        }
        if (lane == 0) {
            out[(size_t)t * DD + d0] = (s0 + b2[e * DD + d0]) * scale;
            out[(size_t)t * DD + d1] = (s1 + b2[e * DD + d1]) * scale;
        }
    }
}

// ---------------------------------------------------------------------------
extern "C" void kernel_launch(void* const* d_in, const int* in_sizes, int n_in,
                              void* d_out, int out_size) {
    const float* x  = (const float*)d_in[0];
    const float* Wr = (const float*)d_in[1];
    const float* W1 = (const float*)d_in[2];
    const float* b1 = (const float*)d_in[3];
    const float* W2 = (const float*)d_in[4];
    const float* b2 = (const float*)d_in[5];
    float* out = (float*)d_out;
    (void)in_sizes; (void)n_in;

    if (out_size > TOKENS * DD) {
        cudaMemsetAsync(out + (size_t)TOKENS * DD, 0,
                        sizeof(float) * (size_t)(out_size - TOKENS * DD), 0);
    }

    router_kernel<<<RBLK, 256>>>(x, Wr, out);
    scan_kernel<<<1, 512>>>(out, out_size);
    ffn1_kernel<<<dim3(FF / 16, EE), 256>>>(x, W1, b1);
    ffn2_kernel<<<dim3(DD / 16, EE), 256>>>(W2, b2, out);
}

// round 16
// speedup vs baseline: 1.9160x; 1.9160x over previous
#include <cuda_runtime.h>
#include <math.h>

// ---------------------------------------------------------------------------
// SwitchMoE: B=8,T=2048,D=1024,F=4096,E=16 -> tokens=16384
// capacity=1280, K=13. Only per-expert rank%1280==0 tokens are processed.
// nonzero(size=K, fill_value=0) artifact: token 0's expert output is scaled
// by (K - kept_e0 + 1). Kept tokens are unique -> plain stores into zeroed
// output (zeroing fused into router).
// ---------------------------------------------------------------------------

#define TOKENS 16384
#define DD     1024
#define EE     16
#define FF     4096
#define CAP    1280
#define KK     13
#define NW     (EE * KK)          /* 208 */
#define RBLK   1024               /* router blocks (16 tokens each) */

// ---- device scratch (no allocations allowed) ------------------------------
__device__ int   g_top1[TOKENS];
__device__ float g_top1p[TOKENS];
__device__ float g_part[EE * RBLK];      // [e][blk] softmax partial sums
__device__ int   g_cnt [EE * RBLK];      // [e][blk] per-block top1 counts
__device__ int   g_wtok[NW];
__device__ float g_wscale[NW];
__device__ float g_h[(size_t)NW * FF];   // ~3.4 MB

// ---------------------------------------------------------------------------
// Router: 16 tokens/block (8 warps x 2 tokens). Wr staged in shared (two
// 8-expert passes); x rows in registers. Emits per-block expert counts and
// prob partial sums (transposed layouts). Zeroes this block's output rows.
// ---------------------------------------------------------------------------
__global__ void __launch_bounds__(256)
router_kernel(const float* __restrict__ x,
              const float* __restrict__ Wr,
              float* __restrict__ out) {
    __shared__ float sWr[8 * DD];        // 32 KB
    __shared__ float sProbs[16][EE + 1];
    __shared__ int   sTop[16];

    const int tid  = threadIdx.x;
    const int warp = tid >> 5;
    const int lane = tid & 31;
    const int tBase = blockIdx.x * 16;
    const int t0 = tBase + warp * 2;

    // zero the 16 output rows this block owns
    {
        float4* o = (float4*)(out + (size_t)tBase * DD);
        const float4 z = make_float4(0.f, 0.f, 0.f, 0.f);
        #pragma unroll
        for (int j = tid; j < 16 * DD / 4; j += 256) o[j] = z;
    }

    float4 xa[8], xb[8];
    {
        const float4* X0 = (const float4*)(x + (size_t)t0 * DD);
        const float4* X1 = (const float4*)(x + (size_t)(t0 + 1) * DD);
        #pragma unroll
        for (int i = 0; i < 8; i++) { xa[i] = X0[lane + i * 32]; xb[i] = X1[lane + i * 32]; }
    }

    float acc0[EE], acc1[EE];
    #pragma unroll
    for (int e = 0; e < EE; e++) { acc0[e] = 0.f; acc1[e] = 0.f; }

    #pragma unroll
    for (int pass = 0; pass < 2; pass++) {
        __syncthreads();
        {
            const float4* wsrc = (const float4*)(Wr + (size_t)pass * 8 * DD);
            float4* sdst = (float4*)sWr;
            #pragma unroll
            for (int j = tid; j < 8 * DD / 4; j += 256) sdst[j] = wsrc[j];
        }
        __syncthreads();
        #pragma unroll
        for (int e8 = 0; e8 < 8; e8++) {
            const float4* w = (const float4*)(sWr + e8 * DD);
            float s0 = 0.f, s1 = 0.f;
            #pragma unroll
            for (int i = 0; i < 8; i++) {
                float4 wv = w[lane + i * 32];
                s0 += xa[i].x * wv.x + xa[i].y * wv.y + xa[i].z * wv.z + xa[i].w * wv.w;
                s1 += xb[i].x * wv.x + xb[i].y * wv.y + xb[i].z * wv.z + xb[i].w * wv.w;
            }
            acc0[pass * 8 + e8] += s0;
            acc1[pass * 8 + e8] += s1;
        }
    }

    #pragma unroll
    for (int off = 16; off; off >>= 1) {
        #pragma unroll
        for (int e = 0; e < EE; e++) {
            acc0[e] += __shfl_xor_sync(0xffffffffu, acc0[e], off);
            acc1[e] += __shfl_xor_sync(0xffffffffu, acc1[e], off);
        }
    }

    if (lane < 2) {
        const float* a = lane ? acc1 : acc0;
        const int t = t0 + lane;
        float m = a[0]; int am = 0;
        #pragma unroll
        for (int e = 1; e < EE; e++) if (a[e] > m) { m = a[e]; am = e; }
        float p[EE];
        float s = 0.f;
        #pragma unroll
        for (int e = 0; e < EE; e++) { p[e] = expf(a[e] - m); s += p[e]; }
        const float inv = 1.0f / s;
        g_top1[t]  = am;
        g_top1p[t] = p[am] * inv;
        sTop[warp * 2 + lane] = am;
        #pragma unroll
        for (int e = 0; e < EE; e++) sProbs[warp * 2 + lane][e] = p[e] * inv;
    }
    __syncthreads();
    if (tid < EE) {
        float s = 0.f;
        int   c = 0;
        #pragma unroll
        for (int j = 0; j < 16; j++) {
            s += sProbs[j][tid];
            c += (sTop[j] == tid);
        }
        g_part[tid * RBLK + blockIdx.x] = s;
        g_cnt [tid * RBLK + blockIdx.x] = c;
    }
}

// ---------------------------------------------------------------------------
// Scan: 1 block, 512 threads. Warp e: shfl prefix-scan over 1024 per-block
// counts (no memory-dependent serial chain), detect blocks containing a
// rank%CAP==0 position (<=28 triples), resolve each triple from 16 tokens.
// Also reduces g_part -> lb_loss and zeroes the output tail.
// ---------------------------------------------------------------------------
__global__ void __launch_bounds__(512)
scan_kernel(float* __restrict__ out, int out_size) {
    const int tid  = threadIdx.x;
    const int wrp  = tid >> 5;
    const int lane = tid & 31;
    __shared__ int   sCnt[EE];
    __shared__ float sPsum[EE];
    __shared__ int   sTrip[64];
    __shared__ int   sNtrip;

    if (tid == 0) sNtrip = 0;
    if (tid < NW) { g_wtok[tid] = -1; g_wscale[tid] = 0.f; }

    // zero any output tail beyond the main tensor + lb slot
    for (int i = TOKENS * DD + 1 + tid; i < out_size; i += 512) out[i] = 0.f;
    __syncthreads();

    // prefix scan of per-block counts for expert wrp
    {
        const int e = wrp;
        int carry = 0;
        for (int i = 0; i < RBLK / 32; i++) {
            const int c = g_cnt[e * RBLK + i * 32 + lane];
            int s = c;
            #pragma unroll
            for (int off = 1; off < 32; off <<= 1) {
                const int n = __shfl_up_sync(0xffffffffu, s, off);
                if (lane >= off) s += n;
            }
            const int excl = carry + s - c;     // exclusive prefix (global rank of first match)
            if (c > 0) {
                const int m = ((excl + CAP - 1) / CAP) * CAP;  // first CAP multiple >= excl
                if (m < excl + c) {             // CAP=1280 > 16 -> at most one per block
                    const int slot = m / CAP;   // <= 12
                    const int ord  = m - excl;  // ordinal within this 16-token block
                    const int pos = atomicAdd(&sNtrip, 1);
                    sTrip[pos] = (e << 18) | ((i * 32 + lane) << 8) | (ord << 4) | slot;
                }
            }
            carry += __shfl_sync(0xffffffffu, s, 31);
        }
        if (lane == 0) sCnt[e] = carry;
    }

    // psum: warp e reduces g_part[e][*] (coalesced)
    {
        const int e = wrp;
        float s = 0.f;
        for (int i = 0; i < RBLK / 32; i++)
            s += g_part[e * RBLK + i * 32 + lane];
        #pragma unroll
        for (int off = 16; off; off >>= 1) s += __shfl_xor_sync(0xffffffffu, s, off);
        if (lane == 0) sPsum[e] = s;
    }
    __syncthreads();

    // resolve triples: find the ord-th token with top1==e inside block blk
    if (tid < sNtrip) {
        const int pk   = sTrip[tid];
        const int e    = pk >> 18;
        const int blk  = (pk >> 8) & 1023;
        const int ord  = (pk >> 4) & 15;
        const int slot = pk & 15;
        int vals[16];
        #pragma unroll
        for (int j = 0; j < 16; j++) vals[j] = g_top1[blk * 16 + j];
        int c = 0, t = 0;
        #pragma unroll
        for (int j = 0; j < 16; j++) {
            if (vals[j] == e) { if (c == ord) t = blk * 16 + j; c++; }
        }
        g_wtok[e * KK + slot]   = t;
        g_wscale[e * KK + slot] = g_top1p[t];
    }
    __syncthreads();

    if (tid == 0) {
        // nonzero(size=K, fill_value=0) artifact
        const int e0 = g_top1[0];
        const int c0 = sCnt[e0];
        const int kept0 = (c0 - 1) / CAP + 1;
        g_wscale[e0 * KK + 0] *= (float)(KK - kept0 + 1);

        if (out_size > TOKENS * DD) {
            float lb = 0.f;
            for (int j = 0; j < EE; j++)
                lb += ((float)sCnt[j] / (float)TOKENS) * (sPsum[j] / (float)TOKENS);
            out[(size_t)TOKENS * DD] = lb * (float)EE * 0.01f;
        }
    }
}

// ---------------------------------------------------------------------------
// FFN1: h = gelu(W1[e] @ x[t] + b1[e]); 4 rows/warp (32 LDG.128 in flight).
// grid(F/32, E).
// ---------------------------------------------------------------------------
__global__ void __launch_bounds__(256)
ffn1_kernel(const float* __restrict__ x,
            const float* __restrict__ W1,
            const float* __restrict__ b1) {
    __shared__ float sx[DD];
    const int tid  = threadIdx.x;
    const int warp = tid >> 5;
    const int lane = tid & 31;
    const int e    = blockIdx.y;
    const int fb   = blockIdx.x * 8 + warp;

    for (int k = 0; k < KK; k++) {
        const int t = g_wtok[e * KK + k];
        if (t < 0) break;
        __syncthreads();
        ((float4*)sx)[tid] = ((const float4*)(x + (size_t)t * DD))[tid];
        __syncthreads();

        const float4* w0 = (const float4*)(W1 + ((size_t)e * FF + fb + 0 * (FF/4)) * DD);
        const float4* w1 = (const float4*)(W1 + ((size_t)e * FF + fb + 1 * (FF/4)) * DD);
        const float4* w2 = (const float4*)(W1 + ((size_t)e * FF + fb + 2 * (FF/4)) * DD);
        const float4* w3 = (const float4*)(W1 + ((size_t)e * FF + fb + 3 * (FF/4)) * DD);
        const float4* xv = (const float4*)sx;
        float s0 = 0.f, s1 = 0.f, s2 = 0.f, s3 = 0.f;
        #pragma unroll
        for (int i = 0; i < 8; i++) {
            const float4 xx = xv[lane + i * 32];
            const float4 a = w0[lane + i * 32];
            const float4 b = w1[lane + i * 32];
            const float4 c = w2[lane + i * 32];
            const float4 d = w3[lane + i * 32];
            s0 += a.x * xx.x + a.y * xx.y + a.z * xx.z + a.w * xx.w;
            s1 += b.x * xx.x + b.y * xx.y + b.z * xx.z + b.w * xx.w;
            s2 += c.x * xx.x + c.y * xx.y + c.z * xx.z + c.w * xx.w;
            s3 += d.x * xx.x + d.y * xx.y + d.z * xx.z + d.w * xx.w;
        }
        #pragma unroll
        for (int off = 16; off; off >>= 1) {
            s0 += __shfl_xor_sync(0xffffffffu, s0, off);
            s1 += __shfl_xor_sync(0xffffffffu, s1, off);
            s2 += __shfl_xor_sync(0xffffffffu, s2, off);
            s3 += __shfl_xor_sync(0xffffffffu, s3, off);
        }
        if (lane == 0) {
            float* hrow = g_h + ((size_t)(e * KK + k)) * FF;
            const float sv[4] = {s0, s1, s2, s3};
            #pragma unroll
            for (int r = 0; r < 4; r++) {
                const int f = fb + r * (FF / 4);
                const float v = sv[r] + b1[e * FF + f];
                hrow[f] = 0.5f * v * (1.0f + erff(v * 0.70710678118654752f));
            }
        }
    }
}

// ---------------------------------------------------------------------------
// FFN2: out[t] = (W2[e] @ h + b2[e]) * scale; 4 rows/warp. grid(D/32, E).
// Kept tokens unique across experts -> plain store.
// ---------------------------------------------------------------------------
__global__ void __launch_bounds__(256)
ffn2_kernel(const float* __restrict__ W2,
            const float* __restrict__ b2,
            float* __restrict__ out) {
    __shared__ float sh[FF];   // 16 KB
    const int tid  = threadIdx.x;
    const int warp = tid >> 5;
    const int lane = tid & 31;
    const int e    = blockIdx.y;
    const int db   = blockIdx.x * 8 + warp;

    for (int k = 0; k < KK; k++) {
        const int t = g_wtok[e * KK + k];
        if (t < 0) break;
        const float scale = g_wscale[e * KK + k];
        __syncthreads();
        {
            const float4* hs = (const float4*)(g_h + ((size_t)(e * KK + k)) * FF);
            float4* sd = (float4*)sh;
            #pragma unroll
            for (int j = tid; j < FF / 4; j += 256) sd[j] = hs[j];
        }
        __syncthreads();

        const float4* w0 = (const float4*)(W2 + ((size_t)e * DD + db + 0 * (DD/4)) * FF);
        const float4* w1 = (const float4*)(W2 + ((size_t)e * DD + db + 1 * (DD/4)) * FF);
        const float4* w2 = (const float4*)(W2 + ((size_t)e * DD + db + 2 * (DD/4)) * FF);
        const float4* w3 = (const float4*)(W2 + ((size_t)e * DD + db + 3 * (DD/4)) * FF);
        const float4* hv = (const float4*)sh;
        float s0 = 0.f, s1 = 0.f, s2 = 0.f, s3 = 0.f;
        #pragma unroll 8
        for (int i = 0; i < 32; i++) {
            const float4 hh = hv[lane + i * 32];
            const float4 a = w0[lane + i * 32];
            const float4 b = w1[lane + i * 32];
            const float4 c = w2[lane + i * 32];
            const float4 d = w3[lane + i * 32];
            s0 += a.x * hh.x + a.y * hh.y + a.z * hh.z + a.w * hh.w;
            s1 += b.x * hh.x + b.y * hh.y + b.z * hh.z + b.w * hh.w;
            s2 += c.x * hh.x + c.y * hh.y + c.z * hh.z + c.w * hh.w;
            s3 += d.x * hh.x + d.y * hh.y + d.z * hh.z + d.w * hh.w;
        }
        #pragma unroll
        for (int off = 16; off; off >>= 1) {
            s0 += __shfl_xor_sync(0xffffffffu, s0, off);
            s1 += __shfl_xor_sync(0xffffffffu, s1, off);
            s2 += __shfl_xor_sync(0xffffffffu, s2, off);
            s3 += __shfl_xor_sync(0xffffffffu, s3, off);
        }
        if (lane == 0) {
            const float sv[4] = {s0, s1, s2, s3};
            #pragma unroll
            for (int r = 0; r < 4; r++) {
                const int d = db + r * (DD / 4);
                out[(size_t)t * DD + d] = (sv[r] + b2[e * DD + d]) * scale;
            }
        }
    }
}

// ---------------------------------------------------------------------------
extern "C" void kernel_launch(void* const* d_in, const int* in_sizes, int n_in,
                              void* d_out, int out_size) {
    const float* x  = (const float*)d_in[0];
    const float* Wr = (const float*)d_in[1];
    const float* W1 = (const float*)d_in[2];
    const float* b1 = (const float*)d_in[3];
    const float* W2 = (const float*)d_in[4];
    const float* b2 = (const float*)d_in[5];
    float* out = (float*)d_out;
    (void)in_sizes; (void)n_in;

    router_kernel<<<RBLK, 256>>>(x, Wr, out);
    scan_kernel<<<1, 512>>>(out, out_size);
    ffn1_kernel<<<dim3(FF / 32, EE), 256>>>(x, W1, b1);
    ffn2_kernel<<<dim3(DD / 32, EE), 256>>>(W2, b2, out);
}